// round 1
// baseline (speedup 1.0000x reference)
#include <cuda_runtime.h>
#include <math.h>

#define NATOMS 120000
#define MM 12
#define AFL 64
#define EFL 41
#define C2 128            // 2*AFL
#define NCONV 3
#define NCRYS 2400
#define ORIG 92
#define NTYPES 100
#define HFL 128
#define GRID1 592
#define STEPF 0.2f
#define EPSF 1e-5f
#define NEDGE (NATOMS*MM)

// ---------------- device scratch (no allocs allowed) ----------------
__device__ float g_embed[NTYPES*AFL];
__device__ float g_x[NATOMS*AFL];
__device__ float g_xW[NATOMS*2*C2];            // [N,256]: cols 0..127 self, 128..255 nbr
__device__ float g_z[NEDGE*C2];                // 737 MB scratch for pre-activation z
__device__ float g_summed[NATOMS*AFL];
__device__ float g_part1[GRID1*256];
__device__ float g_part2[GRID1*128];
__device__ float g_scale1[C2], g_shift1[C2], g_scale2[AFL], g_shift2[AFL];

__device__ __forceinline__ float spf(float x){ return fmaxf(x,0.f) + log1pf(expf(-fabsf(x))); }
__device__ __forceinline__ float sigf(float x){ return 1.0f/(1.0f+expf(-x)); }

// ---------------- embed table: atom_table @ W_embed ----------------
__global__ void k_embed(const float* __restrict__ at, const float* __restrict__ we){
    int t = blockIdx.x;          // type
    int c = threadIdx.x;         // 0..63
    float s = 0.f;
    for(int o=0;o<ORIG;o++) s = fmaf(at[t*ORIG+o], we[o*AFL+c], s);
    g_embed[t*AFL+c] = s;
}

__global__ void k_gatherx(const int* __restrict__ af){
    int i = blockIdx.x*blockDim.x + threadIdx.x;
    if(i < NATOMS*AFL){
        int n = i >> 6, c = i & 63;
        g_x[i] = g_embed[af[n]*AFL + c];
    }
}

// ---------------- xW gemm: [N,64] @ [64,256] (self||nbr halves) ----------------
__global__ void k_gemm(const float* __restrict__ W){
    __shared__ __align__(16) float sW[64][132];
    __shared__ float sX[32][65];
    const int half = blockIdx.y;   // 0 = self rows 0..63, 1 = nbr rows 64..127
    for(int i=threadIdx.x;i<64*C2;i+=256){
        int k = i >> 7, c = i & 127;
        sW[k][c] = W[(half*AFL + k)*C2 + c];
    }
    const int tx = threadIdx.x & 31;   // col group: cols tx*4..tx*4+3
    const int ty = threadIdx.x >> 5;   // row group: rows ty*4..ty*4+3
    for(int tile=blockIdx.x; tile < NATOMS/32; tile += gridDim.x){
        const int row0 = tile*32;
        __syncthreads();
        for(int i=threadIdx.x;i<32*AFL;i+=256){
            int r = i >> 6, k = i & 63;
            sX[r][k] = g_x[(row0+r)*AFL + k];
        }
        __syncthreads();
        float acc[4][4];
        #pragma unroll
        for(int r=0;r<4;r++){
            #pragma unroll
            for(int c=0;c<4;c++) acc[r][c]=0.f;
        }
        #pragma unroll
        for(int k=0;k<AFL;k++){
            float4 wv = *(const float4*)&sW[k][tx*4];
            #pragma unroll
            for(int r=0;r<4;r++){
                float xv = sX[ty*4+r][k];
                acc[r][0] = fmaf(xv, wv.x, acc[r][0]);
                acc[r][1] = fmaf(xv, wv.y, acc[r][1]);
                acc[r][2] = fmaf(xv, wv.z, acc[r][2]);
                acc[r][3] = fmaf(xv, wv.w, acc[r][3]);
            }
        }
        #pragma unroll
        for(int r=0;r<4;r++){
            float4 o = make_float4(acc[r][0],acc[r][1],acc[r][2],acc[r][3]);
            *(float4*)&g_xW[(row0+ty*4+r)*(2*C2) + half*C2 + tx*4] = o;
        }
    }
}

// ---------------- pass1: z = xWs + gather(xWn) + gauss(d)@W_e + b; stats ----------------
__global__ void k_pass1(const float* __restrict__ Wc, const float* __restrict__ bias,
                        const int* __restrict__ nidx, const float* __restrict__ nd){
    __shared__ __align__(16) float sWe[EFL][132];
    __shared__ float sPart[8][256];
    for(int i=threadIdx.x;i<EFL*C2;i+=256){
        int k = i / C2, c = i % C2;
        sWe[k][c] = Wc[(2*AFL + k)*C2 + c];
    }
    __syncthreads();
    const int warp = threadIdx.x >> 5, lane = threadIdx.x & 31;
    float4 bb = *(const float4*)&bias[lane*4];
    float4 s4 = make_float4(0,0,0,0), q4 = make_float4(0,0,0,0);
    for(int n = blockIdx.x*8 + warp; n < NATOMS; n += GRID1*8){
        float4 xs = *(const float4*)&g_xW[n*(2*C2) + lane*4];
        int myi = 0; float myd = 0.f;
        if(lane < MM){ myi = nidx[n*MM + lane]; myd = nd[n*MM + lane]; }
        #pragma unroll 1
        for(int m=0;m<MM;m++){
            int   j = __shfl_sync(0xffffffffu, myi, m);
            float d = __shfl_sync(0xffffffffu, myd, m);
            int kc = __float2int_rn(d * 5.0f);
            int ks = min(max(kc-3, 0), EFL-8);
            float u = d - STEPF*(float)(ks + lane);
            float gl = expf(-u*u*25.0f);       // lanes 0..7 carry the 8 taps
            float4 xn = *(const float4*)&g_xW[j*(2*C2) + C2 + lane*4];
            float4 z;
            z.x = xs.x + xn.x + bb.x;
            z.y = xs.y + xn.y + bb.y;
            z.z = xs.z + xn.z + bb.z;
            z.w = xs.w + xn.w + bb.w;
            #pragma unroll
            for(int t=0;t<8;t++){
                float g = __shfl_sync(0xffffffffu, gl, t);
                float4 wv = *(const float4*)&sWe[ks+t][lane*4];
                z.x = fmaf(g, wv.x, z.x);
                z.y = fmaf(g, wv.y, z.y);
                z.z = fmaf(g, wv.z, z.z);
                z.w = fmaf(g, wv.w, z.w);
            }
            *(float4*)&g_z[(n*MM + m)*C2 + lane*4] = z;
            s4.x += z.x; s4.y += z.y; s4.z += z.z; s4.w += z.w;
            q4.x = fmaf(z.x,z.x,q4.x); q4.y = fmaf(z.y,z.y,q4.y);
            q4.z = fmaf(z.z,z.z,q4.z); q4.w = fmaf(z.w,z.w,q4.w);
        }
    }
    sPart[warp][lane*4+0] = s4.x; sPart[warp][lane*4+1] = s4.y;
    sPart[warp][lane*4+2] = s4.z; sPart[warp][lane*4+3] = s4.w;
    sPart[warp][128+lane*4+0] = q4.x; sPart[warp][128+lane*4+1] = q4.y;
    sPart[warp][128+lane*4+2] = q4.z; sPart[warp][128+lane*4+3] = q4.w;
    __syncthreads();
    int t = threadIdx.x;
    float s = 0.f;
    #pragma unroll
    for(int w=0;w<8;w++) s += sPart[w][t];
    g_part1[blockIdx.x*256 + t] = s;     // deterministic per-block partial
}

__global__ void k_fold1(const float* __restrict__ g1, const float* __restrict__ b1){
    int t = threadIdx.x;   // 128
    float s = 0.f, q = 0.f;
    for(int b=0;b<GRID1;b++){ s += g_part1[b*256+t]; q += g_part1[b*256+128+t]; }
    const float inv = 1.0f/(float)NEDGE;
    float mean = s*inv;
    float var  = q*inv - mean*mean;
    float sc = g1[t] * rsqrtf(var + EPSF);
    g_scale1[t] = sc;
    g_shift1[t] = b1[t] - mean*sc;
}

// ---------------- pass2: BN1 + sigmoid*softplus + sum over neighbors; stats ----------------
__global__ void k_pass2(){
    __shared__ float sc[C2], sh[C2];
    __shared__ float sPart[8][128];
    if(threadIdx.x < C2){ sc[threadIdx.x] = g_scale1[threadIdx.x]; sh[threadIdx.x] = g_shift1[threadIdx.x]; }
    __syncthreads();
    const int warp = threadIdx.x >> 5, lane = threadIdx.x & 31;
    const int c0 = lane*2;
    float s0=0.f,s1=0.f,q0=0.f,q1=0.f;
    for(int n = blockIdx.x*8 + warp; n < NATOMS; n += GRID1*8){
        float a0=0.f, a1=0.f;
        #pragma unroll 1
        for(int m=0;m<MM;m++){
            int e = (n*MM + m)*C2;
            float2 zf = *(const float2*)&g_z[e + c0];
            float2 zc = *(const float2*)&g_z[e + AFL + c0];
            float f0 = fmaf(zf.x, sc[c0],        sh[c0]);
            float f1 = fmaf(zf.y, sc[c0+1],      sh[c0+1]);
            float h0 = fmaf(zc.x, sc[AFL+c0],    sh[AFL+c0]);
            float h1 = fmaf(zc.y, sc[AFL+c0+1],  sh[AFL+c0+1]);
            a0 += sigf(f0)*spf(h0);
            a1 += sigf(f1)*spf(h1);
        }
        *(float2*)&g_summed[n*AFL + c0] = make_float2(a0, a1);
        s0 += a0; s1 += a1; q0 = fmaf(a0,a0,q0); q1 = fmaf(a1,a1,q1);
    }
    sPart[warp][c0]   = s0; sPart[warp][c0+1]   = s1;
    sPart[warp][AFL+c0] = q0; sPart[warp][AFL+c0+1] = q1;
    __syncthreads();
    int t = threadIdx.x;
    if(t < 128){
        float s = 0.f;
        #pragma unroll
        for(int w=0;w<8;w++) s += sPart[w][t];
        g_part2[blockIdx.x*128 + t] = s;
    }
}

__global__ void k_fold2(const float* __restrict__ g2, const float* __restrict__ b2){
    int t = threadIdx.x;   // 64
    float s = 0.f, q = 0.f;
    for(int b=0;b<GRID1;b++){ s += g_part2[b*128+t]; q += g_part2[b*128+64+t]; }
    const float inv = 1.0f/(float)NATOMS;
    float mean = s*inv;
    float var  = q*inv - mean*mean;
    float sc = g2[t] * rsqrtf(var + EPSF);
    g_scale2[t] = sc;
    g_shift2[t] = b2[t] - mean*sc;
}

__global__ void k_update(){
    int i = blockIdx.x*blockDim.x + threadIdx.x;
    if(i < NATOMS*AFL){
        int c = i & (AFL-1);
        float v = g_x[i] + fmaf(g_summed[i], g_scale2[c], g_shift2[c]);
        g_x[i] = spf(v);
    }
}

// ---------------- pooling + MLP head ----------------
__global__ void k_pool(const int* __restrict__ cnt, const float* __restrict__ fcW,
                       const float* __restrict__ fcb, const float* __restrict__ foW,
                       const float* __restrict__ fob, float* __restrict__ out){
    const int cid = blockIdx.x, t = threadIdx.x, w = t>>5, l = t&31;
    __shared__ float sm[AFL];
    __shared__ int sip[4];
    __shared__ float sfp[4];
    // exclusive prefix of counts -> offset of this crystal
    int part = 0;
    for(int i=t; i<cid; i+=128) part += cnt[i];
    for(int o=16;o;o>>=1) part += __shfl_down_sync(0xffffffffu, part, o);
    if(l==0) sip[w] = part;
    __syncthreads();
    const int off = sip[0]+sip[1]+sip[2]+sip[3];
    const int c = cnt[cid];
    if(t < AFL){
        float s = 0.f;
        for(int a=0;a<c;a++) s += g_x[(off+a)*AFL + t];
        sm[t] = spf(s/(float)c);
    }
    __syncthreads();
    float h = fcb[t];
    for(int k=0;k<AFL;k++) h = fmaf(sm[k], fcW[k*HFL + t], h);
    h = spf(h);
    float v = h * foW[t];
    for(int o=16;o;o>>=1) v += __shfl_down_sync(0xffffffffu, v, o);
    if(l==0) sfp[w] = v;
    __syncthreads();
    if(t==0) out[cid] = sfp[0]+sfp[1]+sfp[2]+sfp[3] + fob[0];
}

// ---------------- launch ----------------
extern "C" void kernel_launch(void* const* d_in, const int* in_sizes, int n_in,
                              void* d_out, int out_size){
    const int*   atom_fea   = (const int*)  d_in[0];
    const float* nbr_fea    = (const float*)d_in[1];
    const int*   nbr_idx    = (const int*)  d_in[2];
    const int*   cnt        = (const int*)  d_in[3];
    const float* atom_table = (const float*)d_in[4];
    const float* W_embed    = (const float*)d_in[5];
    const float* W_conv     = (const float*)d_in[6];
    const float* b_conv     = (const float*)d_in[7];
    const float* bn1_g      = (const float*)d_in[8];
    const float* bn1_b      = (const float*)d_in[9];
    const float* bn2_g      = (const float*)d_in[10];
    const float* bn2_b      = (const float*)d_in[11];
    const float* fc_W       = (const float*)d_in[12];
    const float* fc_b       = (const float*)d_in[13];
    const float* fo_W       = (const float*)d_in[14];
    const float* fo_b       = (const float*)d_in[15];
    float* out = (float*)d_out;

    k_embed<<<NTYPES, AFL>>>(atom_table, W_embed);
    k_gatherx<<<(NATOMS*AFL + 255)/256, 256>>>(atom_fea);

    for(int l=0;l<NCONV;l++){
        const float* W = W_conv + l*(2*AFL+EFL)*C2;
        k_gemm<<<dim3(296,2), 256>>>(W);
        k_pass1<<<GRID1, 256>>>(W, b_conv + l*C2, nbr_idx, nbr_fea);
        k_fold1<<<1, 128>>>(bn1_g + l*C2, bn1_b + l*C2);
        k_pass2<<<GRID1, 256>>>();
        k_fold2<<<1, 64>>>(bn2_g + l*AFL, bn2_b + l*AFL);
        k_update<<<(NATOMS*AFL + 255)/256, 256>>>();
    }
    k_pool<<<NCRYS, 128>>>(cnt, fc_W, fc_b, fo_W, fo_b, out);
}